// round 1
// baseline (speedup 1.0000x reference)
#include <cuda_runtime.h>

#define BATCH   128
#define SEQ     2048
#define DIM     256
#define ADIM    128
#define SPLITS  8
#define ROWS_PER_CTA (SEQ / SPLITS)   // 256
#define TILE_T  64
#define NTILES  (ROWS_PER_CTA / TILE_T)  // 4
#define XS      68                    // padded smem stride for X tile [k][t]
#define NTHREADS 256

// scratch (allocation-free: __device__ globals)
__device__ float g_partial[BATCH * SPLITS * DIM];   // 1 MB
__device__ float g_esum[BATCH * SPLITS];

// ---- packed f32x2 helpers (sm_103a FFMA2: full-rate fp32) ----
__device__ __forceinline__ unsigned long long pk2(float v) {
    unsigned long long r;
    asm("mov.b64 %0, {%1, %1};" : "=l"(r) : "f"(v));
    return r;
}
__device__ __forceinline__ void ffma2(unsigned long long& d,
                                      unsigned long long a,
                                      unsigned long long b) {
    asm("fma.rn.f32x2 %0, %1, %2, %0;" : "+l"(d) : "l"(a), "l"(b));
}
union F2 { unsigned long long u; float2 f; };

// tanh(v) = 1 - 2/(exp(2v)+1): 2 MUFU + few FMA; inf-safe (rcp(inf)=0 -> 1)
__device__ __forceinline__ float fast_tanh(float v) {
    float e = __expf(2.0f * v);
    return 1.0f - __fdividef(2.0f, e + 1.0f);
}

__global__ void __launch_bounds__(NTHREADS, 1)
attn_main(const float* __restrict__ x,
          const float* __restrict__ w,
          const float* __restrict__ bias,
          const float* __restrict__ cvec)
{
    extern __shared__ float sm[];
    float* sW   = sm;                       // 256*128 = 32768 floats
    float* sX   = sW + DIM * ADIM;          // 256*68  = 17408 floats, layout [k][t]
    float* sRed = sX + DIM * XS;            // 64*16   = 1024 floats
    float* sE   = sRed + TILE_T * 16;       // 64 floats

    const int tid   = threadIdx.x;
    const int b     = blockIdx.x / SPLITS;
    const int split = blockIdx.x % SPLITS;
    const int t_base0 = split * ROWS_PER_CTA;

    // ---- load full W [256][128] into smem (same layout as global) ----
    {
        const float4* w4 = (const float4*)w;
        float4* sW4 = (float4*)sW;
        #pragma unroll
        for (int i = 0; i < (DIM * ADIM / 4) / NTHREADS; i++)
            sW4[tid + i * NTHREADS] = w4[tid + i * NTHREADS];
    }

    // thread tile: 4 t-rows x 8 a-cols
    const int grp = tid >> 4;          // 0..15  -> a0
    const int a0  = grp << 3;
    const int t0  = (tid & 15) << 2;   // 0,4,...,60

    float bv[8], cv[8];
    #pragma unroll
    for (int j = 0; j < 8; j++) { bv[j] = bias[a0 + j]; cv[j] = cvec[a0 + j]; }

    float out_acc = 0.0f;      // this thread owns output feature d = tid
    float esum_reg = 0.0f;     // only thread 0 uses it

    __syncthreads();

    for (int tile = 0; tile < NTILES; tile++) {
        const int t_base = t_base0 + tile * TILE_T;

        // ---- stage X tile transposed into smem: sX[k][t] ----
        {
            const int r    = tid >> 2;   // 0..63 row within tile
            const int cgrp = tid & 3;
            const float* xrow = x + ((size_t)b * SEQ + t_base + r) * DIM;
            #pragma unroll
            for (int i = 0; i < 16; i++) {
                float4 v = *(const float4*)(xrow + (cgrp + i * 4) * 4);
                int k0 = (cgrp + i * 4) * 4;
                sX[(k0 + 0) * XS + r] = v.x;
                sX[(k0 + 1) * XS + r] = v.y;
                sX[(k0 + 2) * XS + r] = v.z;
                sX[(k0 + 3) * XS + r] = v.w;
            }
        }
        __syncthreads();

        // ---- GEMM: acc[i][j] = (t0+i) row  x  a-pair (a0+2j, a0+2j+1) ----
        unsigned long long acc[4][4];
        #pragma unroll
        for (int i = 0; i < 4; i++)
            #pragma unroll
            for (int j = 0; j < 4; j++) acc[i][j] = 0ULL;

        #pragma unroll 8
        for (int k = 0; k < DIM; k++) {
            float4 xf = *(const float4*)(sX + k * XS + t0);
            ulonglong2 wa = *(const ulonglong2*)(sW + k * ADIM + a0);
            ulonglong2 wb = *(const ulonglong2*)(sW + k * ADIM + a0 + 4);
            unsigned long long xb0 = pk2(xf.x), xb1 = pk2(xf.y),
                               xb2 = pk2(xf.z), xb3 = pk2(xf.w);
            ffma2(acc[0][0], xb0, wa.x); ffma2(acc[0][1], xb0, wa.y);
            ffma2(acc[0][2], xb0, wb.x); ffma2(acc[0][3], xb0, wb.y);
            ffma2(acc[1][0], xb1, wa.x); ffma2(acc[1][1], xb1, wa.y);
            ffma2(acc[1][2], xb1, wb.x); ffma2(acc[1][3], xb1, wb.y);
            ffma2(acc[2][0], xb2, wa.x); ffma2(acc[2][1], xb2, wa.y);
            ffma2(acc[2][2], xb2, wb.x); ffma2(acc[2][3], xb2, wb.y);
            ffma2(acc[3][0], xb3, wa.x); ffma2(acc[3][1], xb3, wa.y);
            ffma2(acc[3][2], xb3, wb.x); ffma2(acc[3][3], xb3, wb.y);
        }

        // ---- epilogue: tanh + context dot -> partial scores ----
        float sp[4] = {0.f, 0.f, 0.f, 0.f};
        #pragma unroll
        for (int i = 0; i < 4; i++) {
            #pragma unroll
            for (int j = 0; j < 4; j++) {
                F2 v; v.u = acc[i][j];
                sp[i] += cv[2 * j]     * fast_tanh(v.f.x + bv[2 * j]);
                sp[i] += cv[2 * j + 1] * fast_tanh(v.f.y + bv[2 * j + 1]);
            }
        }
        #pragma unroll
        for (int i = 0; i < 4; i++) sRed[(t0 + i) * 16 + grp] = sp[i];
        __syncthreads();

        // ---- deterministic score reduction + exp ----
        if (tid < TILE_T) {
            float s = 0.0f;
            #pragma unroll
            for (int g = 0; g < 16; g++) s += sRed[tid * 16 + g];
            sE[tid] = __expf(s);
        }
        __syncthreads();

        if (tid == 0) {
            float es = 0.0f;
            #pragma unroll
            for (int t = 0; t < TILE_T; t++) es += sE[t];
            esum_reg += es;
        }

        // ---- weighted accumulation: out_acc += sum_t e[t] * x[t][d] ----
        // lane-skewed t order -> conflict-free smem reads
        {
            const int l = tid & 31;
            #pragma unroll 8
            for (int t = 0; t < TILE_T; t++) {
                int tt = (t + l) & (TILE_T - 1);
                out_acc = fmaf(sE[tt], sX[tid * XS + tt], out_acc);
            }
        }
        __syncthreads();   // protect sX / sE before next tile overwrites
    }

    g_partial[((size_t)b * SPLITS + split) * DIM + tid] = out_acc;
    if (tid == 0) g_esum[b * SPLITS + split] = esum_reg;
}

__global__ void attn_finish(float* __restrict__ out)
{
    const int b = blockIdx.x;
    const int d = threadIdx.x;
    float s = 0.0f, es = 0.0f;
    #pragma unroll
    for (int sp = 0; sp < SPLITS; sp++) {
        s  += g_partial[((size_t)b * SPLITS + sp) * DIM + d];
        es += g_esum[b * SPLITS + sp];
    }
    out[b * DIM + d] = s / (es + 1e-10f);
}

extern "C" void kernel_launch(void* const* d_in, const int* in_sizes, int n_in,
                              void* d_out, int out_size)
{
    const float* x    = (const float*)d_in[0];
    const float* w    = (const float*)d_in[1];
    const float* bias = (const float*)d_in[2];
    const float* cvec = (const float*)d_in[3];
    float* out = (float*)d_out;

    const size_t smem_bytes =
        (DIM * ADIM + DIM * XS + TILE_T * 16 + TILE_T) * sizeof(float);
    cudaFuncSetAttribute(attn_main,
                         cudaFuncAttributeMaxDynamicSharedMemorySize,
                         (int)smem_bytes);

    attn_main<<<BATCH * SPLITS, NTHREADS, smem_bytes>>>(x, w, bias, cvec);
    attn_finish<<<BATCH, DIM>>>(out);
}

// round 4
// speedup vs baseline: 2.0778x; 2.0778x over previous
#include <cuda_runtime.h>
#include <cuda_bf16.h>
#include <stdint.h>

// ---------------- problem constants ----------------
#define NBATCH 128
#define SEQ    2048
#define DIM    256          // K (features)
#define ADIM   128          // N (attention dim)
#define TILES  2048         // M-tiles of 128 rows
#define GRID   152
#define NTHR   256

// smem layout (bytes)
#define SM_WF     0                  // 131072: W fragments (uint4 per (j,nf,lane))
#define OFF_SSC   131072             // float[128] scores
#define OFF_SE    (131072 + 512)     // float[128] exp(score)
#define OFF_SBIAS (131072 + 1024)    // float[128]
#define OFF_SCV   (131072 + 1536)    // float[128]
#define SM_TOTAL  (131072 + 2048)

// ---------------- device scratch ----------------
__device__ float g_partial[TILES * DIM];          // 2 MB
__device__ float g_esum[TILES];
__device__ uint4 g_Wfrag[16 * 16 * 32];           // [kstep][nfrag][lane] = {hi0,hi1,lo0,lo1}

// ---------------- helpers ----------------
__device__ __forceinline__ uint32_t pkbf(float a, float b) {
    __nv_bfloat162 t = __floats2bfloat162_rn(a, b);
    return *(uint32_t*)&t;
}
__device__ __forceinline__ void split2(float a, float b, uint32_t& hi, uint32_t& lo) {
    float ra = __bfloat162float(__float2bfloat16(a));
    float rb = __bfloat162float(__float2bfloat16(b));
    hi = pkbf(a, b);
    lo = pkbf(a - ra, b - rb);
}
__device__ __forceinline__ void mma_bf16(float c[4], uint32_t a0, uint32_t a1,
                                         uint32_t a2, uint32_t a3,
                                         uint32_t b0, uint32_t b1) {
    asm volatile(
        "mma.sync.aligned.m16n8k16.row.col.f32.bf16.bf16.f32 "
        "{%0,%1,%2,%3}, {%4,%5,%6,%7}, {%8,%9}, {%0,%1,%2,%3};"
        : "+f"(c[0]), "+f"(c[1]), "+f"(c[2]), "+f"(c[3])
        : "r"(a0), "r"(a1), "r"(a2), "r"(a3), "r"(b0), "r"(b1));
}
__device__ __forceinline__ float fast_tanh(float v) {
    float e = __expf(2.0f * v);
    return 1.0f - __fdividef(2.0f, e + 1.0f);
}

// ---------------- W pre-conversion into fragment layout ----------------
// B frag (m16n8k16 col): thread(lane): n = nf*8 + (lane>>2);
//   b0 = {W[k0][n], W[k0+1][n]}, b1 = {W[k0+8][n], W[k0+9][n]}, k0 = 16*j + 2*(lane&3)
__global__ void wprep(const float* __restrict__ w) {
    int idx = blockIdx.x * 256 + threadIdx.x;      // 8192 total
    if (idx >= 16 * 16 * 32) return;
    int lane = idx & 31, nf = (idx >> 5) & 15, j = idx >> 9;
    int g = lane >> 2, tig = lane & 3;
    int n = nf * 8 + g;
    int k0 = j * 16 + tig * 2;
    float w00 = w[(k0 + 0) * ADIM + n], w01 = w[(k0 + 1) * ADIM + n];
    float w80 = w[(k0 + 8) * ADIM + n], w81 = w[(k0 + 9) * ADIM + n];
    uint4 v;
    split2(w00, w01, v.x, v.z);
    split2(w80, w81, v.y, v.w);
    g_Wfrag[idx] = v;
}

// ---------------- main persistent kernel ----------------
__global__ void __launch_bounds__(NTHR, 1)
attn_mma(const float* __restrict__ x,
         const float* __restrict__ bias,
         const float* __restrict__ cvec)
{
    extern __shared__ char smem[];
    uint4* sWf   = (uint4*)(smem + SM_WF);
    float* sSc   = (float*)(smem + OFF_SSC);
    float* sE    = (float*)(smem + OFF_SE);
    float* sBias = (float*)(smem + OFF_SBIAS);
    float* sCv   = (float*)(smem + OFF_SCV);

    const int tid  = threadIdx.x;
    const int wid  = tid >> 5;
    const int lane = tid & 31;
    const int g    = lane >> 2;      // 0..7
    const int tig  = lane & 3;       // 0..3

    if (tid < 128) { sBias[tid] = bias[tid]; sCv[tid] = cvec[tid]; }
    {   // copy W fragments from L2 into smem
        #pragma unroll
        for (int i = 0; i < 32; i++) sWf[tid + i * NTHR] = g_Wfrag[tid + i * NTHR];
    }
    __syncthreads();

    for (int T = blockIdx.x; T < TILES; T += gridDim.x) {
        const size_t row0 = (size_t)T * 128;
        // this thread's two A rows
        const float* xr1 = x + (row0 + (size_t)(wid * 16 + g)) * DIM + 2 * tig;
        const float* xr2 = xr1 + (size_t)8 * DIM;

        float acc[16][4];
        #pragma unroll
        for (int nf = 0; nf < 16; nf++)
            #pragma unroll
            for (int c = 0; c < 4; c++) acc[nf][c] = 0.0f;

        // software pipeline: prefetch k-step j+1 while doing MMAs for j
        float2 n0 = *(const float2*)(xr1);
        float2 n1 = *(const float2*)(xr2);
        float2 n2 = *(const float2*)(xr1 + 8);
        float2 n3 = *(const float2*)(xr2 + 8);

        #pragma unroll 1
        for (int j = 0; j < 16; j++) {
            float2 c0 = n0, c1 = n1, c2 = n2, c3 = n3;
            if (j < 15) {
                int o = (j + 1) * 16;
                n0 = *(const float2*)(xr1 + o);
                n1 = *(const float2*)(xr2 + o);
                n2 = *(const float2*)(xr1 + o + 8);
                n3 = *(const float2*)(xr2 + o + 8);
            }
            // convert to A fragments (hi / lo)
            uint32_t ah0, ah1, ah2, ah3, al0, al1, al2, al3;
            split2(c0.x, c0.y, ah0, al0);   // row g,    k-lo
            split2(c1.x, c1.y, ah1, al1);   // row g+8,  k-lo
            split2(c2.x, c2.y, ah2, al2);   // row g,    k-hi
            split2(c3.x, c3.y, ah3, al3);   // row g+8,  k-hi

            const uint4* bp = sWf + (j * 16) * 32 + lane;
            #pragma unroll
            for (int nf = 0; nf < 16; nf++) {
                uint4 B = bp[nf * 32];
                mma_bf16(acc[nf], ah0, ah1, ah2, ah3, B.x, B.y);   // hi*hi
                mma_bf16(acc[nf], ah0, ah1, ah2, ah3, B.z, B.w);   // hi*lo
                mma_bf16(acc[nf], al0, al1, al2, al3, B.x, B.y);   // lo*hi
            }
        }

        // ---- score: s[t] = sum_a cv[a] * tanh(acc + bias[a]) ----
        float p1 = 0.0f, p2 = 0.0f;
        #pragma unroll
        for (int nf = 0; nf < 16; nf++) {
            int col = nf * 8 + 2 * tig;
            p1 += sCv[col]     * fast_tanh(acc[nf][0] + sBias[col]);
            p1 += sCv[col + 1] * fast_tanh(acc[nf][1] + sBias[col + 1]);
            p2 += sCv[col]     * fast_tanh(acc[nf][2] + sBias[col]);
            p2 += sCv[col + 1] * fast_tanh(acc[nf][3] + sBias[col + 1]);
        }
        p1 += __shfl_xor_sync(0xFFFFFFFFu, p1, 1);
        p1 += __shfl_xor_sync(0xFFFFFFFFu, p1, 2);
        p2 += __shfl_xor_sync(0xFFFFFFFFu, p2, 1);
        p2 += __shfl_xor_sync(0xFFFFFFFFu, p2, 2);
        if (tig == 0) {
            sSc[wid * 16 + g]     = p1;
            sSc[wid * 16 + g + 8] = p2;
        }
        __syncthreads();

        if (tid < 128) sE[tid] = __expf(sSc[tid]);
        __syncthreads();

        if (tid < 32) {
            float e = sE[tid] + sE[tid + 32] + sE[tid + 64] + sE[tid + 96];
            e += __shfl_xor_sync(0xFFFFFFFFu, e, 16);
            e += __shfl_xor_sync(0xFFFFFFFFu, e, 8);
            e += __shfl_xor_sync(0xFFFFFFFFu, e, 4);
            e += __shfl_xor_sync(0xFFFFFFFFu, e, 2);
            e += __shfl_xor_sync(0xFFFFFFFFu, e, 1);
            if (tid == 0) g_esum[T] = e;
        }

        // ---- weighted sum: out[d] += e_t * x[t][d] (x tile is L2-hot) ----
        {
            float a = 0.0f;
            const float* xb = x + row0 * DIM + tid;
            #pragma unroll 8
            for (int t = 0; t < 128; t++)
                a = fmaf(sE[t], __ldg(xb + (size_t)t * DIM), a);
            g_partial[(size_t)T * DIM + tid] = a;
        }
        // sE/sSc protected by the first __syncthreads of next iteration
    }
}

// ---------------- combine ----------------
__global__ void attn_finish(float* __restrict__ out) {
    const int b = blockIdx.x, d = threadIdx.x;
    float s = 0.0f, es = 0.0f;
    #pragma unroll
    for (int sp = 0; sp < 16; sp++) {
        s  += g_partial[(size_t)(b * 16 + sp) * DIM + d];
        es += g_esum[b * 16 + sp];
    }
    out[b * DIM + d] = s / (es + 1e-10f);
}

extern "C" void kernel_launch(void* const* d_in, const int* in_sizes, int n_in,
                              void* d_out, int out_size)
{
    const float* x    = (const float*)d_in[0];
    const float* w    = (const float*)d_in[1];
    const float* bias = (const float*)d_in[2];
    const float* cvec = (const float*)d_in[3];
    float* out = (float*)d_out;

    cudaFuncSetAttribute(attn_mma, cudaFuncAttributeMaxDynamicSharedMemorySize, SM_TOTAL);

    wprep<<<32, 256>>>(w);
    attn_mma<<<GRID, NTHR, SM_TOTAL>>>(x, bias, cvec);
    attn_finish<<<NBATCH, DIM>>>(out);
}

// round 5
// speedup vs baseline: 2.3703x; 1.1408x over previous
#include <cuda_runtime.h>
#include <cuda_bf16.h>
#include <stdint.h>

// ---------------- problem constants ----------------
#define NBATCH 128
#define SEQ    2048
#define DIM    256          // K (features)
#define ADIM   128          // N (attention dim)
#define TILES  2048         // M-tiles of 128 rows
#define GRID   152
#define NTHR   256

// smem layout (bytes)
#define SM_WF     0                   // 131072: W fragments (uint4 per (j,nf,lane))
#define OFF_SE    131072              // float[2][128] exp(score), double buffered
#define OFF_SBIAS (131072 + 1024)     // float[128]
#define OFF_SCV   (131072 + 1536)     // float[128]
#define SM_TOTAL  (131072 + 2048)

// ---------------- device scratch ----------------
__device__ float g_partial[TILES * DIM];          // 2 MB
__device__ float g_esum[TILES];
__device__ uint4 g_Wfrag[16 * 16 * 32];           // [kstep][nfrag][lane] = {hi0,hi1,lo0,lo1}

// ---------------- helpers ----------------
__device__ __forceinline__ uint32_t pkbf(float a, float b) {
    __nv_bfloat162 t = __floats2bfloat162_rn(a, b);
    return *(uint32_t*)&t;
}
__device__ __forceinline__ void split2(float a, float b, uint32_t& hi, uint32_t& lo) {
    float ra = __bfloat162float(__float2bfloat16(a));
    float rb = __bfloat162float(__float2bfloat16(b));
    hi = pkbf(a, b);
    lo = pkbf(a - ra, b - rb);
}
__device__ __forceinline__ void mma_bf16(float c[4], uint32_t a0, uint32_t a1,
                                         uint32_t a2, uint32_t a3,
                                         uint32_t b0, uint32_t b1) {
    asm volatile(
        "mma.sync.aligned.m16n8k16.row.col.f32.bf16.bf16.f32 "
        "{%0,%1,%2,%3}, {%4,%5,%6,%7}, {%8,%9}, {%0,%1,%2,%3};"
        : "+f"(c[0]), "+f"(c[1]), "+f"(c[2]), "+f"(c[3])
        : "r"(a0), "r"(a1), "r"(a2), "r"(a3), "r"(b0), "r"(b1));
}
__device__ __forceinline__ float fast_tanh(float v) {
    float e = __expf(2.0f * v);
    return 1.0f - __fdividef(2.0f, e + 1.0f);
}

// ---------------- W pre-conversion into fragment layout ----------------
// B frag (m16n8k16 col): lane: n = nf*8 + (lane>>2);
//   b0 = {W[k0][n], W[k0+1][n]}, b1 = {W[k0+8][n], W[k0+9][n]}, k0 = 16*j + 2*(lane&3)
__global__ void wprep(const float* __restrict__ w) {
    int idx = blockIdx.x * 256 + threadIdx.x;      // 8192 total
    if (idx >= 16 * 16 * 32) return;
    int lane = idx & 31, nf = (idx >> 5) & 15, j = idx >> 9;
    int g = lane >> 2, tig = lane & 3;
    int n = nf * 8 + g;
    int k0 = j * 16 + tig * 2;
    float w00 = w[(k0 + 0) * ADIM + n], w01 = w[(k0 + 1) * ADIM + n];
    float w80 = w[(k0 + 8) * ADIM + n], w81 = w[(k0 + 9) * ADIM + n];
    uint4 v;
    split2(w00, w01, v.x, v.z);
    split2(w80, w81, v.y, v.w);
    g_Wfrag[idx] = v;
}

// ---------------- main persistent kernel ----------------
__global__ void __launch_bounds__(NTHR, 1)
attn_mma(const float* __restrict__ x,
         const float* __restrict__ bias,
         const float* __restrict__ cvec)
{
    extern __shared__ char smem[];
    uint4* sWf   = (uint4*)(smem + SM_WF);
    float* sE0   = (float*)(smem + OFF_SE);          // [2][128]
    float* sBias = (float*)(smem + OFF_SBIAS);
    float* sCv   = (float*)(smem + OFF_SCV);

    const int tid  = threadIdx.x;
    const int wid  = tid >> 5;
    const int lane = tid & 31;
    const int g    = lane >> 2;      // 0..7
    const int tig  = lane & 3;       // 0..3

    if (tid < 128) { sBias[tid] = bias[tid]; sCv[tid] = cvec[tid]; }
    {   // copy W fragments from L2 into smem
        #pragma unroll
        for (int i = 0; i < 32; i++) sWf[tid + i * NTHR] = g_Wfrag[tid + i * NTHR];
    }
    __syncthreads();

    int lastT = -1, lastbuf = 0;

    int it = 0;
    for (int T = blockIdx.x; T < TILES; T += gridDim.x, it++) {
        const int buf = it & 1;
        const size_t row0 = (size_t)T * 128;
        const float* xr1 = x + (row0 + (size_t)(wid * 16 + g)) * DIM + 2 * tig;
        const float* xr2 = xr1 + (size_t)8 * DIM;

        // weighted-sum state for previous tile (interleaved into this j-loop)
        const int Tprev = T - GRID;
        const bool havePrev = (it > 0);
        const float* xprev = x + ((size_t)(havePrev ? Tprev : T) * 128) * DIM + tid;
        const float* sEp = sE0 + (buf ^ 1) * 128;
        float wacc = 0.0f;

        float acc[16][4];
        #pragma unroll
        for (int nf = 0; nf < 16; nf++)
            #pragma unroll
            for (int c = 0; c < 4; c++) acc[nf][c] = 0.0f;

        float2 n0 = *(const float2*)(xr1);
        float2 n1 = *(const float2*)(xr2);
        float2 n2 = *(const float2*)(xr1 + 8);
        float2 n3 = *(const float2*)(xr2 + 8);

        #pragma unroll 1
        for (int j = 0; j < 16; j++) {
            // ---- issue prev-tile weighted-sum loads early (hide under MMAs) ----
            float wv[8];
            if (havePrev) {
                #pragma unroll
                for (int q = 0; q < 8; q++)
                    wv[q] = __ldg(xprev + (size_t)(j * 8 + q) * DIM);
            }

            float2 c0 = n0, c1 = n1, c2 = n2, c3 = n3;
            if (j < 15) {
                int o = (j + 1) * 16;
                n0 = *(const float2*)(xr1 + o);
                n1 = *(const float2*)(xr2 + o);
                n2 = *(const float2*)(xr1 + o + 8);
                n3 = *(const float2*)(xr2 + o + 8);
            }
            uint32_t ah0, ah1, ah2, ah3, al0, al1, al2, al3;
            split2(c0.x, c0.y, ah0, al0);
            split2(c1.x, c1.y, ah1, al1);
            split2(c2.x, c2.y, ah2, al2);
            split2(c3.x, c3.y, ah3, al3);

            const uint4* bp = sWf + (j * 16) * 32 + lane;
            #pragma unroll
            for (int nf = 0; nf < 16; nf++) {
                uint4 B = bp[nf * 32];
                mma_bf16(acc[nf], ah0, ah1, ah2, ah3, B.x, B.y);   // hi*hi
                mma_bf16(acc[nf], ah0, ah1, ah2, ah3, B.z, B.w);   // hi*lo
                mma_bf16(acc[nf], al0, al1, al2, al3, B.x, B.y);   // lo*hi
            }

            // ---- consume weighted-sum loads ----
            if (havePrev) {
                #pragma unroll
                for (int q = 0; q < 8; q++)
                    wacc = fmaf(sEp[j * 8 + q], wv[q], wacc);
            }
        }

        if (havePrev)
            g_partial[(size_t)Tprev * DIM + tid] = wacc;

        // ---- score + exp directly into sE[buf] ----
        {
            float p1 = 0.0f, p2 = 0.0f;
            #pragma unroll
            for (int nf = 0; nf < 16; nf++) {
                int col = nf * 8 + 2 * tig;
                p1 += sCv[col]     * fast_tanh(acc[nf][0] + sBias[col]);
                p1 += sCv[col + 1] * fast_tanh(acc[nf][1] + sBias[col + 1]);
                p2 += sCv[col]     * fast_tanh(acc[nf][2] + sBias[col]);
                p2 += sCv[col + 1] * fast_tanh(acc[nf][3] + sBias[col + 1]);
            }
            p1 += __shfl_xor_sync(0xFFFFFFFFu, p1, 1);
            p1 += __shfl_xor_sync(0xFFFFFFFFu, p1, 2);
            p2 += __shfl_xor_sync(0xFFFFFFFFu, p2, 1);
            p2 += __shfl_xor_sync(0xFFFFFFFFu, p2, 2);
            if (tig == 0) {
                float* sEc = sE0 + buf * 128;
                sEc[wid * 16 + g]     = __expf(p1);
                sEc[wid * 16 + g + 8] = __expf(p2);
            }
        }
        __syncthreads();

        if (tid < 32) {
            const float* sEc = sE0 + buf * 128;
            float e = sEc[tid] + sEc[tid + 32] + sEc[tid + 64] + sEc[tid + 96];
            e += __shfl_xor_sync(0xFFFFFFFFu, e, 16);
            e += __shfl_xor_sync(0xFFFFFFFFu, e, 8);
            e += __shfl_xor_sync(0xFFFFFFFFu, e, 4);
            e += __shfl_xor_sync(0xFFFFFFFFu, e, 2);
            e += __shfl_xor_sync(0xFFFFFFFFu, e, 1);
            if (tid == 0) g_esum[T] = e;
        }

        lastT = T; lastbuf = buf;
    }

    // ---- drain: weighted sum for the final tile ----
    if (lastT >= 0) {
        const float* sEc = sE0 + lastbuf * 128;
        const float* xprev = x + (size_t)lastT * 128 * DIM + tid;
        float wacc = 0.0f;
        #pragma unroll 16
        for (int t = 0; t < 128; t++)
            wacc = fmaf(sEc[t], __ldg(xprev + (size_t)t * DIM), wacc);
        g_partial[(size_t)lastT * DIM + tid] = wacc;
    }
}

// ---------------- combine ----------------
__global__ void attn_finish(float* __restrict__ out) {
    const int b = blockIdx.x, d = threadIdx.x;
    float s = 0.0f, es = 0.0f;
    #pragma unroll
    for (int sp = 0; sp < 16; sp++) {
        s  += g_partial[(size_t)(b * 16 + sp) * DIM + d];
        es += g_esum[b * 16 + sp];
    }
    out[b * DIM + d] = s / (es + 1e-10f);
}

extern "C" void kernel_launch(void* const* d_in, const int* in_sizes, int n_in,
                              void* d_out, int out_size)
{
    const float* x    = (const float*)d_in[0];
    const float* w    = (const float*)d_in[1];
    const float* bias = (const float*)d_in[2];
    const float* cvec = (const float*)d_in[3];
    float* out = (float*)d_out;

    cudaFuncSetAttribute(attn_mma, cudaFuncAttributeMaxDynamicSharedMemorySize, SM_TOTAL);

    wprep<<<32, 256>>>(w);
    attn_mma<<<GRID, NTHR, SM_TOTAL>>>(x, bias, cvec);
    attn_finish<<<NBATCH, DIM>>>(out);
}